// round 1
// baseline (speedup 1.0000x reference)
#include <cuda_runtime.h>
#include <cuda_bf16.h>
#include <stdint.h>

#define NNODES 50000
#define NEDGES 800000
#define NTILES (NEDGES / 128)
#define PW 68              // smem pitch in 32-bit words (136 bf16 halves per row)

#define HAB_SMEM (2 * 128 * PW * 4)        // 69632
#define EDGE_SMEM 112384

// scratch (static device allocations are allowed)
__device__ __nv_bfloat16 g_hAB[(size_t)NNODES * 256];
__device__ float g_agg[NNODES * 9];

__device__ __forceinline__ uint32_t packbf(float a, float b) {
    __nv_bfloat162 h = __floats2bfloat162_rn(a, b);
    return *reinterpret_cast<uint32_t*>(&h);
}
__device__ __forceinline__ float2 unpackbf(uint32_t u) {
    __nv_bfloat162 h;
    *reinterpret_cast<uint32_t*>(&h) = u;
    return __bfloat1622float2(h);
}
__device__ __forceinline__ void mma16816(float* c, const uint32_t* a, const uint32_t* b) {
    asm volatile(
        "mma.sync.aligned.m16n8k16.row.col.f32.bf16.bf16.f32 "
        "{%0,%1,%2,%3}, {%4,%5,%6,%7}, {%8,%9}, {%0,%1,%2,%3};\n"
        : "+f"(c[0]), "+f"(c[1]), "+f"(c[2]), "+f"(c[3])
        : "r"(a[0]), "r"(a[1]), "r"(a[2]), "r"(a[3]), "r"(b[0]), "r"(b[1]));
}
__device__ __forceinline__ float silu_f(float x) {
    return __fdividef(x, 1.0f + __expf(-x));
}

// ---------------------------------------------------------------------------
// Precompute hAB[n][0:128] = h[n] @ W1[0:128,:], hAB[n][128:256] = h[n] @ W1[128:256,:]
// grid (ceil(N/128), 2), block 256
// ---------------------------------------------------------------------------
__global__ void __launch_bounds__(256, 2)
hab_kernel(const float* __restrict__ h, const float* __restrict__ W1) {
    extern __shared__ unsigned char sm[];
    uint32_t* Hs = (uint32_t*)sm;
    __nv_bfloat16* Hh = (__nv_bfloat16*)sm;
    uint32_t* Bs = (uint32_t*)(sm + 128 * PW * 4);
    __nv_bfloat16* Bh = (__nv_bfloat16*)(sm + 128 * PW * 4);

    const int tid = threadIdx.x;
    const int nt0 = blockIdx.x * 128;
    const int hb = blockIdx.y;   // 0 -> W1 rows [0,128), 1 -> rows [128,256)

    for (int idx = tid; idx < 128 * 128; idx += 256) {
        int i = idx >> 7, k = idx & 127;
        float v = (nt0 + i < NNODES) ? h[(size_t)(nt0 + i) * 128 + k] : 0.f;
        Hh[i * 136 + k] = __float2bfloat16(v);
    }
    for (int idx = tid; idx < 128 * 128; idx += 256) {
        int i = idx >> 7, j = idx & 127;
        Bh[j * 136 + i] = __float2bfloat16(W1[(size_t)(hb * 128 + i) * 128 + j]);
    }
    __syncthreads();

    const int warp = tid >> 5, lane = tid & 31;
    const int wr = warp & 3, wc = warp >> 2;
    const int R0 = wr * 32, C0 = wc * 64;
    const int g = lane >> 2, t = lane & 3;

    float acc[2][8][4];
#pragma unroll
    for (int mt = 0; mt < 2; mt++)
#pragma unroll
        for (int nt = 0; nt < 8; nt++)
#pragma unroll
            for (int u = 0; u < 4; u++) acc[mt][nt][u] = 0.f;

#pragma unroll
    for (int kb = 0; kb < 8; kb++) {
        int kw = kb * 8;
        uint32_t a[2][4];
#pragma unroll
        for (int mt = 0; mt < 2; mt++) {
            int ra = R0 + 16 * mt + g;
            a[mt][0] = Hs[ra * PW + kw + t];
            a[mt][1] = Hs[(ra + 8) * PW + kw + t];
            a[mt][2] = Hs[ra * PW + kw + t + 4];
            a[mt][3] = Hs[(ra + 8) * PW + kw + t + 4];
        }
#pragma unroll
        for (int nt = 0; nt < 8; nt++) {
            uint32_t b[2];
            int nb = C0 + 8 * nt + g;
            b[0] = Bs[nb * PW + kw + t];
            b[1] = Bs[nb * PW + kw + t + 4];
            mma16816(acc[0][nt], a[0], b);
            mma16816(acc[1][nt], a[1], b);
        }
    }

    uint32_t* outw = (uint32_t*)g_hAB;
#pragma unroll
    for (int mt = 0; mt < 2; mt++)
#pragma unroll
        for (int nt = 0; nt < 8; nt++) {
            int rr = R0 + 16 * mt + g;
            int cc = C0 + 8 * nt + 2 * t;
            int n0 = nt0 + rr;
            if (n0 < NNODES)
                outw[((size_t)n0 * 256 + hb * 128 + cc) >> 1] = packbf(acc[mt][nt][0], acc[mt][nt][1]);
            int n1 = nt0 + rr + 8;
            if (n1 < NNODES)
                outw[((size_t)n1 * 256 + hb * 128 + cc) >> 1] = packbf(acc[mt][nt][2], acc[mt][nt][3]);
        }
}

__global__ void zero_agg_kernel() {
    int i = blockIdx.x * 256 + threadIdx.x;
    if (i < NNODES * 9) g_agg[i] = 0.f;
}

// ---------------------------------------------------------------------------
// Fused edge kernel: gather + LN + SiLU -> GEMM(W2) -> LN + SiLU -> GEMM(W3pad)
//                   -> 3x3 transform -> atomic scatter
// ---------------------------------------------------------------------------
__global__ void __launch_bounds__(256, 2)
edge_kernel(const float* __restrict__ W1, const float* __restrict__ b1,
            const float* __restrict__ g1, const float* __restrict__ be1,
            const float* __restrict__ W2, const float* __restrict__ b2,
            const float* __restrict__ g2, const float* __restrict__ be2,
            const float* __restrict__ W3,
            const int* __restrict__ rowI, const int* __restrict__ colI,
            const float* __restrict__ edge_attr, const float* __restrict__ edge_mask,
            const float* __restrict__ coord_diff) {
    extern __shared__ unsigned char sm[];
    uint32_t* X1w = (uint32_t*)sm;                      // 128 x PW words (34816 B)
    float* X3s = (float*)sm;                            // overlays X1 (128 x 17 f32)
    uint32_t* X2w = (uint32_t*)(sm + 34816);            // 34816 B
    uint32_t* W2Tw = (uint32_t*)(sm + 69632);           // 34816 B
    __nv_bfloat16* W2Th = (__nv_bfloat16*)(sm + 69632);
    uint32_t* W3Tw = (uint32_t*)(sm + 104448);          // 16 x 136 bf16 (4352 B)
    __nv_bfloat16* W3Th = (__nv_bfloat16*)(sm + 104448);
    float* par = (float*)(sm + 108800);                 // 7 x 128 f32
    float* w1c = par;
    float* sb1 = par + 128; float* sg1 = par + 256; float* sbe1 = par + 384;
    float* sb2 = par + 512; float* sg2 = par + 640; float* sbe2 = par + 768;

    const int tid = threadIdx.x;
    if (tid < 128) {
        w1c[tid] = W1[256 * 128 + tid];
        sb1[tid] = b1[tid]; sg1[tid] = g1[tid]; sbe1[tid] = be1[tid];
        sb2[tid] = b2[tid]; sg2[tid] = g2[tid]; sbe2[tid] = be2[tid];
    }
    for (int idx = tid; idx < 128 * 128; idx += 256) {
        int i = idx >> 7, j = idx & 127;
        W2Th[j * 136 + i] = __float2bfloat16(W2[idx]);
    }
    for (int idx = tid; idx < 16 * 128; idx += 256) {
        int n = idx >> 7, k = idx & 127;
        W3Th[n * 136 + k] = __float2bfloat16(n < 9 ? W3[k * 9 + n] : 0.f);
    }
    __syncthreads();

    const int warp = tid >> 5, lane = tid & 31;
    const int g = lane >> 2, t = lane & 3;
    const int wr = warp & 3, wc = warp >> 2;
    const int R0 = wr * 32, C0 = wc * 64;
    const int j0 = lane * 4;

    for (int tile = blockIdx.x; tile < NTILES; tile += gridDim.x) {
        const int ebase = tile * 128;

        // ---- Stage A: gather hA[row]+hB[col]+ea*w1c+b1, LN, SiLU -> X1 (bf16) ----
#pragma unroll 2
        for (int it = 0; it < 16; ++it) {
            int el = warp * 16 + it;
            int e = ebase + el;
            int r = rowI[e], c = colI[e];
            float ea = edge_attr[e];
            uint2 wa = *(const uint2*)(g_hAB + (size_t)r * 256 + j0);
            uint2 wb = *(const uint2*)(g_hAB + (size_t)c * 256 + 128 + j0);
            float2 a0 = unpackbf(wa.x), a1 = unpackbf(wa.y);
            float2 f0 = unpackbf(wb.x), f1 = unpackbf(wb.y);
            float x[4];
            x[0] = a0.x + f0.x + ea * w1c[j0] + sb1[j0];
            x[1] = a0.y + f0.y + ea * w1c[j0 + 1] + sb1[j0 + 1];
            x[2] = a1.x + f1.x + ea * w1c[j0 + 2] + sb1[j0 + 2];
            x[3] = a1.y + f1.y + ea * w1c[j0 + 3] + sb1[j0 + 3];
            float s = x[0] + x[1] + x[2] + x[3];
            float q = x[0] * x[0] + x[1] * x[1] + x[2] * x[2] + x[3] * x[3];
#pragma unroll
            for (int o = 16; o > 0; o >>= 1) {
                s += __shfl_xor_sync(0xffffffffu, s, o);
                q += __shfl_xor_sync(0xffffffffu, q, o);
            }
            float mean = s * (1.f / 128.f);
            float var = q * (1.f / 128.f) - mean * mean;
            float rs = rsqrtf(var + 1e-5f);
            float y[4];
#pragma unroll
            for (int u = 0; u < 4; u++) {
                float v = (x[u] - mean) * rs * sg1[j0 + u] + sbe1[j0 + u];
                y[u] = silu_f(v);
            }
            *(uint2*)&X1w[el * PW + lane * 2] = make_uint2(packbf(y[0], y[1]), packbf(y[2], y[3]));
        }
        __syncthreads();

        // ---- GEMM1: X2pre = X1 @ W2  (128x128x128 bf16 HMMA) ----
        {
            float acc[2][8][4];
#pragma unroll
            for (int mt = 0; mt < 2; mt++)
#pragma unroll
                for (int nt = 0; nt < 8; nt++)
#pragma unroll
                    for (int u = 0; u < 4; u++) acc[mt][nt][u] = 0.f;

#pragma unroll
            for (int kb = 0; kb < 8; kb++) {
                int kw = kb * 8;
                uint32_t a[2][4];
#pragma unroll
                for (int mt = 0; mt < 2; mt++) {
                    int ra = R0 + 16 * mt + g;
                    a[mt][0] = X1w[ra * PW + kw + t];
                    a[mt][1] = X1w[(ra + 8) * PW + kw + t];
                    a[mt][2] = X1w[ra * PW + kw + t + 4];
                    a[mt][3] = X1w[(ra + 8) * PW + kw + t + 4];
                }
#pragma unroll
                for (int nt = 0; nt < 8; nt++) {
                    uint32_t b[2];
                    int nb = C0 + 8 * nt + g;
                    b[0] = W2Tw[nb * PW + kw + t];
                    b[1] = W2Tw[nb * PW + kw + t + 4];
                    mma16816(acc[0][nt], a[0], b);
                    mma16816(acc[1][nt], a[1], b);
                }
            }
            // store pre-activation (+b2) to X2 (bf16)
#pragma unroll
            for (int mt = 0; mt < 2; mt++)
#pragma unroll
                for (int nt = 0; nt < 8; nt++) {
                    int rr = R0 + 16 * mt + g;
                    int cc = C0 + 8 * nt + 2 * t;
                    X2w[rr * PW + (cc >> 1)] =
                        packbf(acc[mt][nt][0] + sb2[cc], acc[mt][nt][1] + sb2[cc + 1]);
                    X2w[(rr + 8) * PW + (cc >> 1)] =
                        packbf(acc[mt][nt][2] + sb2[cc], acc[mt][nt][3] + sb2[cc + 1]);
                }
        }
        __syncthreads();

        // ---- LN2 + SiLU in place on X2 ----
#pragma unroll 2
        for (int it = 0; it < 16; ++it) {
            int el = warp * 16 + it;
            uint2 wv = *(uint2*)&X2w[el * PW + lane * 2];
            float2 u0 = unpackbf(wv.x), u1 = unpackbf(wv.y);
            float x[4] = {u0.x, u0.y, u1.x, u1.y};
            float s = x[0] + x[1] + x[2] + x[3];
            float q = x[0] * x[0] + x[1] * x[1] + x[2] * x[2] + x[3] * x[3];
#pragma unroll
            for (int o = 16; o > 0; o >>= 1) {
                s += __shfl_xor_sync(0xffffffffu, s, o);
                q += __shfl_xor_sync(0xffffffffu, q, o);
            }
            float mean = s * (1.f / 128.f);
            float var = q * (1.f / 128.f) - mean * mean;
            float rs = rsqrtf(var + 1e-5f);
            float y[4];
#pragma unroll
            for (int u = 0; u < 4; u++) {
                float v = (x[u] - mean) * rs * sg2[j0 + u] + sbe2[j0 + u];
                y[u] = silu_f(v);
            }
            *(uint2*)&X2w[el * PW + lane * 2] = make_uint2(packbf(y[0], y[1]), packbf(y[2], y[3]));
        }
        __syncthreads();

        // ---- GEMM2: X3 = X2 @ W3pad (128x16x128), warps 0..3 only ----
        if (warp < 4) {
            float a3[2][2][4];
#pragma unroll
            for (int mt = 0; mt < 2; mt++)
#pragma unroll
                for (int nt = 0; nt < 2; nt++)
#pragma unroll
                    for (int u = 0; u < 4; u++) a3[mt][nt][u] = 0.f;

#pragma unroll
            for (int kb = 0; kb < 8; kb++) {
                int kw = kb * 8;
                uint32_t a[2][4];
#pragma unroll
                for (int mt = 0; mt < 2; mt++) {
                    int ra = warp * 32 + 16 * mt + g;
                    a[mt][0] = X2w[ra * PW + kw + t];
                    a[mt][1] = X2w[(ra + 8) * PW + kw + t];
                    a[mt][2] = X2w[ra * PW + kw + t + 4];
                    a[mt][3] = X2w[(ra + 8) * PW + kw + t + 4];
                }
#pragma unroll
                for (int nt = 0; nt < 2; nt++) {
                    uint32_t b[2];
                    int nb = 8 * nt + g;
                    b[0] = W3Tw[nb * PW + kw + t];
                    b[1] = W3Tw[nb * PW + kw + t + 4];
                    mma16816(a3[0][nt], a[0], b);
                    mma16816(a3[1][nt], a[1], b);
                }
            }
#pragma unroll
            for (int mt = 0; mt < 2; mt++)
#pragma unroll
                for (int nt = 0; nt < 2; nt++) {
                    int rr = warp * 32 + 16 * mt + g;
                    int cc = 8 * nt + 2 * t;
                    X3s[rr * 17 + cc] = a3[mt][nt][0];
                    X3s[rr * 17 + cc + 1] = a3[mt][nt][1];
                    X3s[(rr + 8) * 17 + cc] = a3[mt][nt][2];
                    X3s[(rr + 8) * 17 + cc + 1] = a3[mt][nt][3];
                }
        }
        __syncthreads();

        // ---- Stage E: trans[l][k] = sum_j cd[j][k] * phi[j][l]; atomic scatter ----
        if (tid < 128) {
            int e = ebase + tid;
            int r = rowI[e];
            float em = edge_mask[e];
            float ph[9];
#pragma unroll
            for (int c9 = 0; c9 < 9; c9++) ph[c9] = X3s[tid * 17 + c9];
            float cd[9];
            const float* cdp = coord_diff + (size_t)e * 9;
#pragma unroll
            for (int c9 = 0; c9 < 9; c9++) cd[c9] = cdp[c9];
#pragma unroll
            for (int l = 0; l < 3; l++)
#pragma unroll
                for (int k = 0; k < 3; k++) {
                    float tr = cd[k] * ph[l] + cd[3 + k] * ph[3 + l] + cd[6 + k] * ph[6 + l];
                    atomicAdd(&g_agg[r * 9 + l * 3 + k], tr * em);
                }
        }
        __syncthreads();
    }
}

__global__ void finalize_kernel(const float* __restrict__ coord,
                                const float* __restrict__ node_mask,
                                float* __restrict__ out) {
    int i = blockIdx.x * 256 + threadIdx.x;
    if (i < NNODES * 9) {
        out[i] = (coord[i] + g_agg[i] * 0.01f) * node_mask[i / 9];
    }
}

extern "C" void kernel_launch(void* const* d_in, const int* in_sizes, int n_in,
                              void* d_out, int out_size) {
    const float* h          = (const float*)d_in[0];
    const float* coord      = (const float*)d_in[1];
    const float* coord_diff = (const float*)d_in[2];
    const float* edge_attr  = (const float*)d_in[3];
    const float* edge_mask  = (const float*)d_in[4];
    const float* node_mask  = (const float*)d_in[5];
    const int*   rowI       = (const int*)d_in[6];
    const int*   colI       = (const int*)d_in[7];
    const float* W1  = (const float*)d_in[8];
    const float* b1  = (const float*)d_in[9];
    const float* g1  = (const float*)d_in[10];
    const float* be1 = (const float*)d_in[11];
    const float* W2  = (const float*)d_in[12];
    const float* b2  = (const float*)d_in[13];
    const float* g2  = (const float*)d_in[14];
    const float* be2 = (const float*)d_in[15];
    const float* W3  = (const float*)d_in[16];
    float* out = (float*)d_out;

    cudaFuncSetAttribute(hab_kernel, cudaFuncAttributeMaxDynamicSharedMemorySize, HAB_SMEM);
    cudaFuncSetAttribute(edge_kernel, cudaFuncAttributeMaxDynamicSharedMemorySize, EDGE_SMEM);

    hab_kernel<<<dim3((NNODES + 127) / 128, 2), 256, HAB_SMEM>>>(h, W1);
    zero_agg_kernel<<<(NNODES * 9 + 255) / 256, 256>>>();
    edge_kernel<<<296, 256, EDGE_SMEM>>>(W1, b1, g1, be1, W2, b2, g2, be2, W3,
                                         rowI, colI, edge_attr, edge_mask, coord_diff);
    finalize_kernel<<<(NNODES * 9 + 255) / 256, 256>>>(coord, node_mask, out);
}

// round 2
// speedup vs baseline: 1.2451x; 1.2451x over previous
#include <cuda_runtime.h>
#include <cuda_bf16.h>
#include <stdint.h>

#define NNODES 50000
#define NEDGES 800000
#define MTILE 64
#define NTILES (NEDGES / MTILE)   // 12500

// ---------------- scratch ----------------
__device__ __align__(128) __nv_bfloat16 g_hAB[(size_t)NNODES * 256];
__device__ __align__(128) __nv_bfloat16 g_W1T[2 * 128 * 128];
__device__ float g_sA[NNODES];
__device__ float g_sB[NNODES];
__device__ float g_agg[NNODES * 9];

// ---------------- helpers ----------------
static __device__ __forceinline__ uint32_t packbf(float a, float b) {
    __nv_bfloat162 h = __floats2bfloat162_rn(a, b);
    return *reinterpret_cast<uint32_t*>(&h);
}
static __device__ __forceinline__ float2 unpackbf(uint32_t u) {
    __nv_bfloat162 h; *reinterpret_cast<uint32_t*>(&h) = u;
    return __bfloat1622float2(h);
}
static __device__ __forceinline__ void mma16816(float* c, const uint32_t* a, const uint32_t* b) {
    asm volatile(
        "mma.sync.aligned.m16n8k16.row.col.f32.bf16.bf16.f32 "
        "{%0,%1,%2,%3}, {%4,%5,%6,%7}, {%8,%9}, {%0,%1,%2,%3};\n"
        : "+f"(c[0]), "+f"(c[1]), "+f"(c[2]), "+f"(c[3])
        : "r"(a[0]), "r"(a[1]), "r"(a[2]), "r"(a[3]), "r"(b[0]), "r"(b[1]));
}
static __device__ __forceinline__ void ldsm4(uint32_t* r, uint32_t addr) {
    asm volatile("ldmatrix.sync.aligned.m8n8.x4.shared.b16 {%0,%1,%2,%3}, [%4];"
        : "=r"(r[0]), "=r"(r[1]), "=r"(r[2]), "=r"(r[3]) : "r"(addr));
}
static __device__ __forceinline__ float silu_f(float x) {
    return __fdividef(x, 1.0f + __expf(-x));
}
static __device__ __forceinline__ uint32_t s2u(const void* p) {
    return (uint32_t)__cvta_generic_to_shared(p);
}

// ---------------------------------------------------------------------------
// prep: W1 -> bf16 transposed halves; zero agg
// ---------------------------------------------------------------------------
__global__ void prep_kernel(const float* __restrict__ W1) {
    int i = blockIdx.x * 256 + threadIdx.x;
    if (i < 2 * 128 * 128) {
        int hb = i >> 14, n = (i >> 7) & 127, k = i & 127;
        g_W1T[i] = __float2bfloat16(W1[(size_t)(hb * 128 + k) * 128 + n]);
    }
    if (i < NNODES * 9) g_agg[i] = 0.f;
}

// ---------------------------------------------------------------------------
// hab: hA' = h @ W1[0:128] + b1 ; hB = h @ W1[128:256]; row sums to g_sA/g_sB
// grid (782, 2), block 256
// ---------------------------------------------------------------------------
#define HAB_SMEM (17408 + 34816 + 1024)
__global__ void __launch_bounds__(256, 2)
hab_kernel(const float* __restrict__ h, const float* __restrict__ b1) {
    extern __shared__ unsigned char sm[];
    unsigned char* smA = sm;             // 64 x 272B
    unsigned char* smB = sm + 17408;     // 128 x 272B
    float* part = (float*)(sm + 52224);  // 64 x 4 floats

    const int tid = threadIdx.x;
    const int nt0 = blockIdx.x * 64;
    const int hb = blockIdx.y;

    for (int idx = tid; idx < 64 * 32; idx += 256) {
        int i = idx >> 5, kq = idx & 31;
        float4 v = make_float4(0.f, 0.f, 0.f, 0.f);
        if (nt0 + i < NNODES) v = *(const float4*)(h + (size_t)(nt0 + i) * 128 + kq * 4);
        *(uint2*)(smA + i * 272 + kq * 8) = make_uint2(packbf(v.x, v.y), packbf(v.z, v.w));
    }
    const uint4* w1src = (const uint4*)(g_W1T + (hb << 14));
    for (int idx = tid; idx < 128 * 16; idx += 256) {
        int n = idx >> 4, q = idx & 15;
        *(uint4*)(smB + n * 272 + q * 16) = w1src[idx];
    }
    __syncthreads();

    const int warp = tid >> 5, lane = tid & 31;
    const int lr = lane & 7, sel = lane >> 3, g = lane >> 2, t = lane & 3;
    const int R0 = (warp & 1) * 32, wc = warp >> 1, C0 = wc * 32;

    uint32_t aAddr[2], bAddr[2];
#pragma unroll
    for (int mt = 0; mt < 2; mt++)
        aAddr[mt] = s2u(smA + (R0 + 16 * mt + lr + (sel & 1) * 8) * 272 + (sel >> 1) * 16);
#pragma unroll
    for (int np = 0; np < 2; np++)
        bAddr[np] = s2u(smB + (C0 + 16 * np + lr + (sel >> 1) * 8) * 272 + (sel & 1) * 16);

    float acc[2][4][4];
#pragma unroll
    for (int mt = 0; mt < 2; mt++)
#pragma unroll
        for (int nt = 0; nt < 4; nt++)
#pragma unroll
            for (int u = 0; u < 4; u++) acc[mt][nt][u] = 0.f;

#pragma unroll
    for (int kb = 0; kb < 8; kb++) {
        uint32_t a[2][4], b[2][4];
        ldsm4(a[0], aAddr[0] + kb * 32);
        ldsm4(a[1], aAddr[1] + kb * 32);
        ldsm4(b[0], bAddr[0] + kb * 32);
        ldsm4(b[1], bAddr[1] + kb * 32);
#pragma unroll
        for (int mt = 0; mt < 2; mt++)
#pragma unroll
            for (int np = 0; np < 2; np++) {
                mma16816(acc[mt][2 * np], a[mt], &b[np][0]);
                mma16816(acc[mt][2 * np + 1], a[mt], &b[np][2]);
            }
    }

    float b1v[8];
#pragma unroll
    for (int nt = 0; nt < 4; nt++) {
        b1v[2 * nt] = (hb == 0) ? b1[C0 + 8 * nt + 2 * t] : 0.f;
        b1v[2 * nt + 1] = (hb == 0) ? b1[C0 + 8 * nt + 2 * t + 1] : 0.f;
    }

    float ps[4] = {0.f, 0.f, 0.f, 0.f};
    uint32_t* outw = (uint32_t*)g_hAB;
#pragma unroll
    for (int mt = 0; mt < 2; mt++)
#pragma unroll
        for (int nt = 0; nt < 4; nt++) {
            float v0 = acc[mt][nt][0] + b1v[2 * nt];
            float v1 = acc[mt][nt][1] + b1v[2 * nt + 1];
            float v2 = acc[mt][nt][2] + b1v[2 * nt];
            float v3 = acc[mt][nt][3] + b1v[2 * nt + 1];
            ps[2 * mt] += v0 + v1;
            ps[2 * mt + 1] += v2 + v3;
            int node0 = nt0 + R0 + 16 * mt + g;
            int cc = C0 + 8 * nt + 2 * t;
            if (node0 < NNODES)
                outw[((size_t)node0 * 256 + (hb << 7) + cc) >> 1] = packbf(v0, v1);
            if (node0 + 8 < NNODES)
                outw[((size_t)(node0 + 8) * 256 + (hb << 7) + cc) >> 1] = packbf(v2, v3);
        }
#pragma unroll
    for (int rl = 0; rl < 4; rl++) {
        ps[rl] += __shfl_xor_sync(0xffffffffu, ps[rl], 1);
        ps[rl] += __shfl_xor_sync(0xffffffffu, ps[rl], 2);
    }
    if (t == 0) {
#pragma unroll
        for (int rl = 0; rl < 4; rl++) {
            int row = R0 + 16 * (rl >> 1) + 8 * (rl & 1) + g;
            part[row * 4 + wc] = ps[rl];
        }
    }
    __syncthreads();
    if (tid < 64) {
        int node = nt0 + tid;
        if (node < NNODES) {
            float s = part[tid * 4] + part[tid * 4 + 1] + part[tid * 4 + 2] + part[tid * 4 + 3];
            if (hb == 0) g_sA[node] = s; else g_sB[node] = s;
        }
    }
}

// ---------------------------------------------------------------------------
// edge kernel: fused gather+LN1+SiLU -> GEMM(W2) -> fused LN2+SiLU -> GEMM(W3)
//              -> 3x3 transform -> atomic scatter.  64-edge tiles.
// ---------------------------------------------------------------------------
#define OFF_XA   0
#define OFF_W2   17408
#define OFF_W3   52224
#define OFF_X3   56576
#define OFF_PART 60928
#define OFF_CD   62976
#define OFF_PAR  66304
#define EDGE_SMEM 69440

__global__ void __launch_bounds__(256, 2)
edge_kernel(const float* __restrict__ W1, const float* __restrict__ g1,
            const float* __restrict__ be1,
            const float* __restrict__ W2, const float* __restrict__ b2,
            const float* __restrict__ g2, const float* __restrict__ be2,
            const float* __restrict__ W3,
            const int* __restrict__ rowI, const int* __restrict__ colI,
            const float* __restrict__ edge_attr, const float* __restrict__ edge_mask,
            const float* __restrict__ coord_diff) {
    extern __shared__ unsigned char sm[];
    unsigned char* smXA = sm + OFF_XA;                 // 64 x 272B (X1, then X2)
    uint32_t* XAw = (uint32_t*)smXA;
    unsigned char* smW2 = sm + OFF_W2;                 // 128 x 272B
    __nv_bfloat16* W2h = (__nv_bfloat16*)smW2;
    unsigned char* smW3 = sm + OFF_W3;                 // 16 x 272B
    __nv_bfloat16* W3h = (__nv_bfloat16*)smW3;
    float* X3s = (float*)(sm + OFF_X3);                // 64 x 17 f32
    float* partp = (float*)(sm + OFF_PART);            // 64 rows x 4 float2
    float* cds = (float*)(sm + OFF_CD);                // 64 x 13 f32
    float* par = (float*)(sm + OFF_PAR);
    float* sw1c = par;           float* sg1 = par + 128;  float* sbe1 = par + 256;
    float* sb2 = par + 384;      float* sg2 = par + 512;  float* sbe2 = par + 640;
    float* sSw = par + 768;

    const int tid = threadIdx.x;
    if (tid < 128) {
        sw1c[tid] = W1[256 * 128 + tid];
        sg1[tid] = g1[tid]; sbe1[tid] = be1[tid];
        sb2[tid] = b2[tid]; sg2[tid] = g2[tid]; sbe2[tid] = be2[tid];
    }
    for (int idx = tid; idx < 128 * 128; idx += 256) {
        int k = idx >> 7, n = idx & 127;
        W2h[n * 136 + k] = __float2bfloat16(W2[idx]);
    }
    for (int idx = tid; idx < 16 * 128; idx += 256) {
        int n = idx >> 7, k = idx & 127;
        W3h[n * 136 + k] = __float2bfloat16(n < 9 ? W3[k * 9 + n] : 0.f);
    }
    __syncthreads();

    const int warp = tid >> 5, lane = tid & 31;
    const int lr = lane & 7, sel = lane >> 3, g = lane >> 2, t = lane & 3;
    const int R0 = (warp & 1) * 32, wc = warp >> 1, C0 = wc * 32;
    const int j0 = lane * 4;

    if (warp == 0) {
        float s = sw1c[lane] + sw1c[lane + 32] + sw1c[lane + 64] + sw1c[lane + 96];
#pragma unroll
        for (int o = 16; o > 0; o >>= 1) s += __shfl_xor_sync(0xffffffffu, s, o);
        if (lane == 0) sSw[0] = s;
    }
    __syncthreads();

    // per-lane parameter registers
    float w1v[4], g1v[4], be1v[4];
#pragma unroll
    for (int u = 0; u < 4; u++) {
        w1v[u] = sw1c[j0 + u]; g1v[u] = sg1[j0 + u]; be1v[u] = sbe1[j0 + u];
    }
    float b2v[8], g2v[8], be2v[8];
#pragma unroll
    for (int nt = 0; nt < 4; nt++)
#pragma unroll
        for (int u = 0; u < 2; u++) {
            int cc = C0 + 8 * nt + 2 * t + u;
            b2v[2 * nt + u] = sb2[cc]; g2v[2 * nt + u] = sg2[cc]; be2v[2 * nt + u] = sbe2[cc];
        }
    const float Sw = sSw[0];

    // ldmatrix base addresses
    uint32_t aAddr[2], bAddr[2];
#pragma unroll
    for (int mt = 0; mt < 2; mt++)
        aAddr[mt] = s2u(smXA + (R0 + 16 * mt + lr + (sel & 1) * 8) * 272 + (sel >> 1) * 16);
#pragma unroll
    for (int np = 0; np < 2; np++)
        bAddr[np] = s2u(smW2 + (C0 + 16 * np + lr + (sel >> 1) * 8) * 272 + (sel & 1) * 16);
    uint32_t aAddr2 = s2u(smXA + ((warp & 3) * 16 + lr + (sel & 1) * 8) * 272 + (sel >> 1) * 16);
    uint32_t bAddr3 = s2u(smW3 + (lr + (sel >> 1) * 8) * 272 + (sel & 1) * 16);

    for (int tile = blockIdx.x; tile < NTILES; tile += gridDim.x) {
        const int ebase = tile * MTILE;

        // ---- Stage A: gather + LN1 + SiLU -> XA (bf16) ----
#pragma unroll 4
        for (int it = 0; it < 8; ++it) {
            int el = warp * 8 + it;
            int e = ebase + el;
            int r = __ldg(rowI + e), c = __ldg(colI + e);
            float ea = __ldg(edge_attr + e);
            float sums = g_sA[r] + g_sB[c];
            uint2 wa = *(const uint2*)(g_hAB + (size_t)r * 256 + j0);
            uint2 wb = *(const uint2*)(g_hAB + (size_t)c * 256 + 128 + j0);
            float2 a0 = unpackbf(wa.x), a1 = unpackbf(wa.y);
            float2 f0 = unpackbf(wb.x), f1 = unpackbf(wb.y);
            float x0 = a0.x + f0.x + ea * w1v[0];
            float x1 = a0.y + f0.y + ea * w1v[1];
            float x2 = a1.x + f1.x + ea * w1v[2];
            float x3 = a1.y + f1.y + ea * w1v[3];
            float q = x0 * x0 + x1 * x1 + x2 * x2 + x3 * x3;
#pragma unroll
            for (int o = 16; o > 0; o >>= 1) q += __shfl_xor_sync(0xffffffffu, q, o);
            float mean = (sums + ea * Sw) * (1.f / 128.f);
            float var = q * (1.f / 128.f) - mean * mean;
            float rsv = rsqrtf(var + 1e-5f);
            float mrs = -mean * rsv;
            float y0 = silu_f(fmaf(fmaf(x0, rsv, mrs), g1v[0], be1v[0]));
            float y1 = silu_f(fmaf(fmaf(x1, rsv, mrs), g1v[1], be1v[1]));
            float y2 = silu_f(fmaf(fmaf(x2, rsv, mrs), g1v[2], be1v[2]));
            float y3 = silu_f(fmaf(fmaf(x3, rsv, mrs), g1v[3], be1v[3]));
            *(uint2*)&XAw[el * 68 + lane * 2] = make_uint2(packbf(y0, y1), packbf(y2, y3));
        }
        __syncthreads();   // sync1

        // ---- GEMM1: acc = X1 @ W2 ----
        float acc[2][4][4];
#pragma unroll
        for (int mt = 0; mt < 2; mt++)
#pragma unroll
            for (int nt = 0; nt < 4; nt++)
#pragma unroll
                for (int u = 0; u < 4; u++) acc[mt][nt][u] = 0.f;
#pragma unroll
        for (int kb = 0; kb < 8; kb++) {
            uint32_t a[2][4], b[2][4];
            ldsm4(a[0], aAddr[0] + kb * 32);
            ldsm4(a[1], aAddr[1] + kb * 32);
            ldsm4(b[0], bAddr[0] + kb * 32);
            ldsm4(b[1], bAddr[1] + kb * 32);
#pragma unroll
            for (int mt = 0; mt < 2; mt++)
#pragma unroll
                for (int np = 0; np < 2; np++) {
                    mma16816(acc[mt][2 * np], a[mt], &b[np][0]);
                    mma16816(acc[mt][2 * np + 1], a[mt], &b[np][2]);
                }
        }
        // bias + per-row partial sums (for LN2)
        float ps[4] = {0.f, 0.f, 0.f, 0.f}, pq[4] = {0.f, 0.f, 0.f, 0.f};
#pragma unroll
        for (int mt = 0; mt < 2; mt++)
#pragma unroll
            for (int nt = 0; nt < 4; nt++) {
                float v0 = acc[mt][nt][0] + b2v[2 * nt];
                float v1 = acc[mt][nt][1] + b2v[2 * nt + 1];
                float v2 = acc[mt][nt][2] + b2v[2 * nt];
                float v3 = acc[mt][nt][3] + b2v[2 * nt + 1];
                acc[mt][nt][0] = v0; acc[mt][nt][1] = v1;
                acc[mt][nt][2] = v2; acc[mt][nt][3] = v3;
                ps[2 * mt] += v0 + v1; pq[2 * mt] += v0 * v0 + v1 * v1;
                ps[2 * mt + 1] += v2 + v3; pq[2 * mt + 1] += v2 * v2 + v3 * v3;
            }
#pragma unroll
        for (int rl = 0; rl < 4; rl++) {
            ps[rl] += __shfl_xor_sync(0xffffffffu, ps[rl], 1);
            ps[rl] += __shfl_xor_sync(0xffffffffu, ps[rl], 2);
            pq[rl] += __shfl_xor_sync(0xffffffffu, pq[rl], 1);
            pq[rl] += __shfl_xor_sync(0xffffffffu, pq[rl], 2);
        }
        if (t == 0) {
#pragma unroll
            for (int rl = 0; rl < 4; rl++) {
                int row = R0 + 16 * (rl >> 1) + 8 * (rl & 1) + g;
                *(float2*)&partp[row * 8 + wc * 2] = make_float2(ps[rl], pq[rl]);
            }
        }
        __syncthreads();   // sync2

        // ---- LN2 + SiLU from registers, write X2 (bf16) into XA ----
        float rsl[4], mrl[4];
#pragma unroll
        for (int rl = 0; rl < 4; rl++) {
            int row = R0 + 16 * (rl >> 1) + 8 * (rl & 1) + g;
            float4 pA = *(const float4*)&partp[row * 8];
            float4 pB = *(const float4*)&partp[row * 8 + 4];
            float s = pA.x + pA.z + pB.x + pB.z;
            float q = pA.y + pA.w + pB.y + pB.w;
            float mean = s * (1.f / 128.f);
            float var = q * (1.f / 128.f) - mean * mean;
            rsl[rl] = rsqrtf(var + 1e-5f);
            mrl[rl] = -mean * rsl[rl];
        }
#pragma unroll
        for (int mt = 0; mt < 2; mt++)
#pragma unroll
            for (int nt = 0; nt < 4; nt++) {
                int rl0 = 2 * mt, rl1 = 2 * mt + 1;
                float y0 = silu_f(fmaf(fmaf(acc[mt][nt][0], rsl[rl0], mrl[rl0]), g2v[2 * nt], be2v[2 * nt]));
                float y1 = silu_f(fmaf(fmaf(acc[mt][nt][1], rsl[rl0], mrl[rl0]), g2v[2 * nt + 1], be2v[2 * nt + 1]));
                float y2 = silu_f(fmaf(fmaf(acc[mt][nt][2], rsl[rl1], mrl[rl1]), g2v[2 * nt], be2v[2 * nt]));
                float y3 = silu_f(fmaf(fmaf(acc[mt][nt][3], rsl[rl1], mrl[rl1]), g2v[2 * nt + 1], be2v[2 * nt + 1]));
                int row = R0 + 16 * mt + g;
                int cw = (C0 + 8 * nt + 2 * t) >> 1;
                XAw[row * 68 + cw] = packbf(y0, y1);
                XAw[(row + 8) * 68 + cw] = packbf(y2, y3);
            }
        __syncthreads();   // sync3

        // ---- GEMM2 (warps 0-3) + coord_diff staging (warps 4-5) ----
        if (warp < 4) {
            float a2[2][4];
#pragma unroll
            for (int nt = 0; nt < 2; nt++)
#pragma unroll
                for (int u = 0; u < 4; u++) a2[nt][u] = 0.f;
#pragma unroll
            for (int kb = 0; kb < 8; kb++) {
                uint32_t aa[4], bb[4];
                ldsm4(aa, aAddr2 + kb * 32);
                ldsm4(bb, bAddr3 + kb * 32);
                mma16816(a2[0], aa, &bb[0]);
                mma16816(a2[1], aa, &bb[2]);
            }
            int row = warp * 16 + g;
#pragma unroll
            for (int nt = 0; nt < 2; nt++) {
                int cc = 8 * nt + 2 * t;
                X3s[row * 17 + cc] = a2[nt][0];
                X3s[row * 17 + cc + 1] = a2[nt][1];
                X3s[(row + 8) * 17 + cc] = a2[nt][2];
                X3s[(row + 8) * 17 + cc + 1] = a2[nt][3];
            }
        } else if (warp < 6) {
            int el2 = tid - 128;
            const float* cdp = coord_diff + (size_t)(ebase + el2) * 9;
#pragma unroll
            for (int c9 = 0; c9 < 9; c9++) cds[el2 * 13 + c9] = __ldg(cdp + c9);
        }
        __syncthreads();   // sync4

        // ---- scatter (warps 4-5) ----
        if (warp >= 4 && warp < 6) {
            int el2 = tid - 128;
            int e2 = ebase + el2;
            int r2 = __ldg(rowI + e2);
            float em = __ldg(edge_mask + e2);
            float ph[9], cd[9];
#pragma unroll
            for (int c9 = 0; c9 < 9; c9++) ph[c9] = X3s[el2 * 17 + c9];
#pragma unroll
            for (int c9 = 0; c9 < 9; c9++) cd[c9] = cds[el2 * 13 + c9];
            float* aggp = g_agg + (size_t)r2 * 9;
#pragma unroll
            for (int l = 0; l < 3; l++)
#pragma unroll
                for (int k = 0; k < 3; k++) {
                    float tr = cd[k] * ph[l] + cd[3 + k] * ph[3 + l] + cd[6 + k] * ph[6 + l];
                    atomicAdd(aggp + l * 3 + k, tr * em);
                }
        }
        // no extra barrier: next Stage A writes XA (dead) and X3s/cds are
        // only rewritten after sync3 of the next tile.
    }
}

__global__ void finalize_kernel(const float* __restrict__ coord,
                                const float* __restrict__ node_mask,
                                float* __restrict__ out) {
    int i = blockIdx.x * 256 + threadIdx.x;
    if (i < NNODES * 9) {
        out[i] = (coord[i] + g_agg[i] * 0.01f) * node_mask[i / 9];
    }
}

extern "C" void kernel_launch(void* const* d_in, const int* in_sizes, int n_in,
                              void* d_out, int out_size) {
    const float* h          = (const float*)d_in[0];
    const float* coord      = (const float*)d_in[1];
    const float* coord_diff = (const float*)d_in[2];
    const float* edge_attr  = (const float*)d_in[3];
    const float* edge_mask  = (const float*)d_in[4];
    const float* node_mask  = (const float*)d_in[5];
    const int*   rowI       = (const int*)d_in[6];
    const int*   colI       = (const int*)d_in[7];
    const float* W1  = (const float*)d_in[8];
    const float* b1  = (const float*)d_in[9];
    const float* g1  = (const float*)d_in[10];
    const float* be1 = (const float*)d_in[11];
    const float* W2  = (const float*)d_in[12];
    const float* b2  = (const float*)d_in[13];
    const float* g2  = (const float*)d_in[14];
    const float* be2 = (const float*)d_in[15];
    const float* W3  = (const float*)d_in[16];
    float* out = (float*)d_out;

    cudaFuncSetAttribute(hab_kernel, cudaFuncAttributeMaxDynamicSharedMemorySize, HAB_SMEM);
    cudaFuncSetAttribute(edge_kernel, cudaFuncAttributeMaxDynamicSharedMemorySize, EDGE_SMEM);

    prep_kernel<<<(NNODES * 9 + 255) / 256, 256>>>(W1);
    hab_kernel<<<dim3((NNODES + 63) / 64, 2), 256, HAB_SMEM>>>(h, b1);
    edge_kernel<<<296, 256, EDGE_SMEM>>>(W1, g1, be1, W2, b2, g2, be2, W3,
                                         rowI, colI, edge_attr, edge_mask, coord_diff);
    finalize_kernel<<<(NNODES * 9 + 255) / 256, 256>>>(coord, node_mask, out);
}

// round 3
// speedup vs baseline: 1.3517x; 1.0856x over previous
#include <cuda_runtime.h>
#include <cuda_bf16.h>
#include <stdint.h>

#define NNODES 50000
#define NEDGES 800000
#define MTILE 64
#define NTILES (NEDGES / MTILE)   // 12500

// ---------------- scratch ----------------
__device__ __align__(128) __nv_bfloat16 g_hAB[(size_t)NNODES * 256];
__device__ __align__(128) __nv_bfloat16 g_W1T[2 * 128 * 128];
__device__ float g_sA[NNODES];
__device__ float g_sB[NNODES];
__device__ float g_agg[NNODES * 9];

// ---------------- helpers ----------------
static __device__ __forceinline__ uint32_t packbf(float a, float b) {
    __nv_bfloat162 h = __floats2bfloat162_rn(a, b);
    return *reinterpret_cast<uint32_t*>(&h);
}
static __device__ __forceinline__ float2 unpackbf(uint32_t u) {
    __nv_bfloat162 h; *reinterpret_cast<uint32_t*>(&h) = u;
    return __bfloat1622float2(h);
}
static __device__ __forceinline__ void mma16816(float* c, const uint32_t* a, const uint32_t* b) {
    asm volatile(
        "mma.sync.aligned.m16n8k16.row.col.f32.bf16.bf16.f32 "
        "{%0,%1,%2,%3}, {%4,%5,%6,%7}, {%8,%9}, {%0,%1,%2,%3};\n"
        : "+f"(c[0]), "+f"(c[1]), "+f"(c[2]), "+f"(c[3])
        : "r"(a[0]), "r"(a[1]), "r"(a[2]), "r"(a[3]), "r"(b[0]), "r"(b[1]));
}
static __device__ __forceinline__ void ldsm4(uint32_t* r, uint32_t addr) {
    asm volatile("ldmatrix.sync.aligned.m8n8.x4.shared.b16 {%0,%1,%2,%3}, [%4];"
        : "=r"(r[0]), "=r"(r[1]), "=r"(r[2]), "=r"(r[3]) : "r"(addr));
}
static __device__ __forceinline__ float silu_f(float x) {
    return __fdividef(x, 1.0f + __expf(-x));
}
static __device__ __forceinline__ uint32_t s2u(const void* p) {
    return (uint32_t)__cvta_generic_to_shared(p);
}

// ---------------------------------------------------------------------------
// prep: W1 -> bf16 transposed halves; zero agg
// ---------------------------------------------------------------------------
__global__ void prep_kernel(const float* __restrict__ W1) {
    int i = blockIdx.x * 256 + threadIdx.x;
    if (i < 2 * 128 * 128) {
        int hb = i >> 14, n = (i >> 7) & 127, k = i & 127;
        g_W1T[i] = __float2bfloat16(W1[(size_t)(hb * 128 + k) * 128 + n]);
    }
    if (i < NNODES * 9) g_agg[i] = 0.f;
}

// ---------------------------------------------------------------------------
// hab: hA' = h @ W1[0:128] + b1 ; hB = h @ W1[128:256]; row sums to g_sA/g_sB
// ---------------------------------------------------------------------------
#define HAB_SMEM (17408 + 34816 + 1024)
__global__ void __launch_bounds__(256, 2)
hab_kernel(const float* __restrict__ h, const float* __restrict__ b1) {
    extern __shared__ unsigned char sm[];
    unsigned char* smA = sm;             // 64 x 272B
    unsigned char* smB = sm + 17408;     // 128 x 272B
    float* part = (float*)(sm + 52224);  // 64 x 4 floats

    const int tid = threadIdx.x;
    const int nt0 = blockIdx.x * 64;
    const int hb = blockIdx.y;

    for (int idx = tid; idx < 64 * 32; idx += 256) {
        int i = idx >> 5, kq = idx & 31;
        float4 v = make_float4(0.f, 0.f, 0.f, 0.f);
        if (nt0 + i < NNODES) v = *(const float4*)(h + (size_t)(nt0 + i) * 128 + kq * 4);
        *(uint2*)(smA + i * 272 + kq * 8) = make_uint2(packbf(v.x, v.y), packbf(v.z, v.w));
    }
    const uint4* w1src = (const uint4*)(g_W1T + (hb << 14));
    for (int idx = tid; idx < 128 * 16; idx += 256) {
        int n = idx >> 4, q = idx & 15;
        *(uint4*)(smB + n * 272 + q * 16) = w1src[idx];
    }
    __syncthreads();

    const int warp = tid >> 5, lane = tid & 31;
    const int lr = lane & 7, sel = lane >> 3, g = lane >> 2, t = lane & 3;
    const int R0 = (warp & 1) * 32, wc = warp >> 1, C0 = wc * 32;

    uint32_t aAddr[2], bAddr[2];
#pragma unroll
    for (int mt = 0; mt < 2; mt++)
        aAddr[mt] = s2u(smA + (R0 + 16 * mt + lr + (sel & 1) * 8) * 272 + (sel >> 1) * 16);
#pragma unroll
    for (int np = 0; np < 2; np++)
        bAddr[np] = s2u(smB + (C0 + 16 * np + lr + (sel >> 1) * 8) * 272 + (sel & 1) * 16);

    float acc[2][4][4];
#pragma unroll
    for (int mt = 0; mt < 2; mt++)
#pragma unroll
        for (int nt = 0; nt < 4; nt++)
#pragma unroll
            for (int u = 0; u < 4; u++) acc[mt][nt][u] = 0.f;

#pragma unroll
    for (int kb = 0; kb < 8; kb++) {
        uint32_t a[2][4], b[2][4];
        ldsm4(a[0], aAddr[0] + kb * 32);
        ldsm4(a[1], aAddr[1] + kb * 32);
        ldsm4(b[0], bAddr[0] + kb * 32);
        ldsm4(b[1], bAddr[1] + kb * 32);
#pragma unroll
        for (int mt = 0; mt < 2; mt++)
#pragma unroll
            for (int np = 0; np < 2; np++) {
                mma16816(acc[mt][2 * np], a[mt], &b[np][0]);
                mma16816(acc[mt][2 * np + 1], a[mt], &b[np][2]);
            }
    }

    float b1v[8];
#pragma unroll
    for (int nt = 0; nt < 4; nt++) {
        b1v[2 * nt] = (hb == 0) ? b1[C0 + 8 * nt + 2 * t] : 0.f;
        b1v[2 * nt + 1] = (hb == 0) ? b1[C0 + 8 * nt + 2 * t + 1] : 0.f;
    }

    float ps[4] = {0.f, 0.f, 0.f, 0.f};
    uint32_t* outw = (uint32_t*)g_hAB;
#pragma unroll
    for (int mt = 0; mt < 2; mt++)
#pragma unroll
        for (int nt = 0; nt < 4; nt++) {
            float v0 = acc[mt][nt][0] + b1v[2 * nt];
            float v1 = acc[mt][nt][1] + b1v[2 * nt + 1];
            float v2 = acc[mt][nt][2] + b1v[2 * nt];
            float v3 = acc[mt][nt][3] + b1v[2 * nt + 1];
            ps[2 * mt] += v0 + v1;
            ps[2 * mt + 1] += v2 + v3;
            int node0 = nt0 + R0 + 16 * mt + g;
            int cc = C0 + 8 * nt + 2 * t;
            if (node0 < NNODES)
                outw[((size_t)node0 * 256 + (hb << 7) + cc) >> 1] = packbf(v0, v1);
            if (node0 + 8 < NNODES)
                outw[((size_t)(node0 + 8) * 256 + (hb << 7) + cc) >> 1] = packbf(v2, v3);
        }
#pragma unroll
    for (int rl = 0; rl < 4; rl++) {
        ps[rl] += __shfl_xor_sync(0xffffffffu, ps[rl], 1);
        ps[rl] += __shfl_xor_sync(0xffffffffu, ps[rl], 2);
    }
    if (t == 0) {
#pragma unroll
        for (int rl = 0; rl < 4; rl++) {
            int row = R0 + 16 * (rl >> 1) + 8 * (rl & 1) + g;
            part[row * 4 + wc] = ps[rl];
        }
    }
    __syncthreads();
    if (tid < 64) {
        int node = nt0 + tid;
        if (node < NNODES) {
            float s = part[tid * 4] + part[tid * 4 + 1] + part[tid * 4 + 2] + part[tid * 4 + 3];
            if (hb == 0) g_sA[node] = s; else g_sB[node] = s;
        }
    }
}

// ---------------------------------------------------------------------------
// edge kernel: fused gather+LN1+SiLU -> GEMM(W2) -> fused LN2+SiLU -> GEMM(W3)
//              -> 3x3 transform -> atomic scatter.  64-edge tiles, 3 CTAs/SM.
// ---------------------------------------------------------------------------
#define OFF_XA   0
#define OFF_W2   17408
#define OFF_W3   52224
#define OFF_X3   56576
#define OFF_PART 60928
#define OFF_CD   62976
#define OFF_PAR  66304
#define EDGE_SMEM 69440

__global__ void __launch_bounds__(256, 3)
edge_kernel(const float* __restrict__ W1, const float* __restrict__ g1,
            const float* __restrict__ be1,
            const float* __restrict__ W2, const float* __restrict__ b2,
            const float* __restrict__ g2, const float* __restrict__ be2,
            const float* __restrict__ W3,
            const int* __restrict__ rowI, const int* __restrict__ colI,
            const float* __restrict__ edge_attr, const float* __restrict__ edge_mask,
            const float* __restrict__ coord_diff) {
    extern __shared__ unsigned char sm[];
    unsigned char* smXA = sm + OFF_XA;                 // 64 x 272B (X1, then X2)
    uint32_t* XAw = (uint32_t*)smXA;
    unsigned char* smW2 = sm + OFF_W2;                 // 128 x 272B
    __nv_bfloat16* W2h = (__nv_bfloat16*)smW2;
    unsigned char* smW3 = sm + OFF_W3;                 // 16 x 272B
    __nv_bfloat16* W3h = (__nv_bfloat16*)smW3;
    float* X3s = (float*)(sm + OFF_X3);                // 64 x 17 f32
    float* partp = (float*)(sm + OFF_PART);            // 64 rows x 4 float2
    float* cds = (float*)(sm + OFF_CD);                // 64 x 13 f32
    float* par = (float*)(sm + OFF_PAR);
    float* sw1c = par;           float* sg1 = par + 128;  float* sbe1 = par + 256;
    float* sb2 = par + 384;      float* sg2 = par + 512;  float* sbe2 = par + 640;
    float* sSw = par + 768;

    const int tid = threadIdx.x;
    if (tid < 128) {
        sw1c[tid] = W1[256 * 128 + tid];
        sg1[tid] = g1[tid]; sbe1[tid] = be1[tid];
        sb2[tid] = b2[tid]; sg2[tid] = g2[tid]; sbe2[tid] = be2[tid];
    }
    for (int idx = tid; idx < 128 * 128; idx += 256) {
        int k = idx >> 7, n = idx & 127;
        W2h[n * 136 + k] = __float2bfloat16(W2[idx]);
    }
    for (int idx = tid; idx < 16 * 128; idx += 256) {
        int n = idx >> 7, k = idx & 127;
        W3h[n * 136 + k] = __float2bfloat16(n < 9 ? W3[k * 9 + n] : 0.f);
    }
    __syncthreads();

    const int warp = tid >> 5, lane = tid & 31;
    const int lr = lane & 7, sel = lane >> 3, g = lane >> 2, t = lane & 3;
    const int R0 = (warp & 1) * 32, wc = warp >> 1, C0 = wc * 32;
    const int j0 = lane * 4;

    if (warp == 0) {
        float s = sw1c[lane] + sw1c[lane + 32] + sw1c[lane + 64] + sw1c[lane + 96];
#pragma unroll
        for (int o = 16; o > 0; o >>= 1) s += __shfl_xor_sync(0xffffffffu, s, o);
        if (lane == 0) sSw[0] = s;
    }
    __syncthreads();

    // per-lane stage-A parameter registers
    float w1v[4], g1v[4], be1v[4];
#pragma unroll
    for (int u = 0; u < 4; u++) {
        w1v[u] = sw1c[j0 + u]; g1v[u] = sg1[j0 + u]; be1v[u] = sbe1[j0 + u];
    }
    const float Sw = sSw[0];

    // ldmatrix base addresses
    uint32_t aAddr[2], bAddr[2];
#pragma unroll
    for (int mt = 0; mt < 2; mt++)
        aAddr[mt] = s2u(smXA + (R0 + 16 * mt + lr + (sel & 1) * 8) * 272 + (sel >> 1) * 16);
#pragma unroll
    for (int np = 0; np < 2; np++)
        bAddr[np] = s2u(smW2 + (C0 + 16 * np + lr + (sel >> 1) * 8) * 272 + (sel & 1) * 16);
    uint32_t aAddr2 = s2u(smXA + ((warp & 3) * 16 + lr + (sel & 1) * 8) * 272 + (sel >> 1) * 16);
    uint32_t bAddr3 = s2u(smW3 + (lr + (sel >> 1) * 8) * 272 + (sel & 1) * 16);

    for (int tile = blockIdx.x; tile < NTILES; tile += gridDim.x) {
        const int ebase = tile * MTILE;
        const int e0 = ebase + warp * 8;

        // ---- Stage A: gather + LN1 + SiLU -> XA (bf16), depth-3 pipeline ----
        int rs8[8], cs8[8]; float eas[8];
#pragma unroll
        for (int it = 0; it < 8; it++) {
            rs8[it] = __ldg(rowI + e0 + it);
            cs8[it] = __ldg(colI + e0 + it);
            eas[it] = __ldg(edge_attr + e0 + it);
        }
        uint2 pwa[3], pwb[3]; float psa[3], psb[3];
#pragma unroll
        for (int p = 0; p < 3; p++) {
            pwa[p] = *(const uint2*)(g_hAB + (size_t)rs8[p] * 256 + j0);
            pwb[p] = *(const uint2*)(g_hAB + (size_t)cs8[p] * 256 + 128 + j0);
            psa[p] = __ldg(g_sA + rs8[p]);
            psb[p] = __ldg(g_sB + cs8[p]);
        }
#pragma unroll
        for (int it = 0; it < 8; it++) {
            const int s = it % 3;
            uint2 wa = pwa[s], wb = pwb[s];
            float sums = psa[s] + psb[s];
            float ea = eas[it];
            if (it + 3 < 8) {
                pwa[s] = *(const uint2*)(g_hAB + (size_t)rs8[it + 3] * 256 + j0);
                pwb[s] = *(const uint2*)(g_hAB + (size_t)cs8[it + 3] * 256 + 128 + j0);
                psa[s] = __ldg(g_sA + rs8[it + 3]);
                psb[s] = __ldg(g_sB + cs8[it + 3]);
            }
            float2 a0 = unpackbf(wa.x), a1 = unpackbf(wa.y);
            float2 f0 = unpackbf(wb.x), f1 = unpackbf(wb.y);
            float x0 = a0.x + f0.x + ea * w1v[0];
            float x1 = a0.y + f0.y + ea * w1v[1];
            float x2 = a1.x + f1.x + ea * w1v[2];
            float x3 = a1.y + f1.y + ea * w1v[3];
            float q = x0 * x0 + x1 * x1 + x2 * x2 + x3 * x3;
#pragma unroll
            for (int o = 16; o > 0; o >>= 1) q += __shfl_xor_sync(0xffffffffu, q, o);
            float mean = (sums + ea * Sw) * (1.f / 128.f);
            float var = q * (1.f / 128.f) - mean * mean;
            float rsv = rsqrtf(var + 1e-5f);
            float mrs = -mean * rsv;
            float y0 = silu_f(fmaf(fmaf(x0, rsv, mrs), g1v[0], be1v[0]));
            float y1 = silu_f(fmaf(fmaf(x1, rsv, mrs), g1v[1], be1v[1]));
            float y2 = silu_f(fmaf(fmaf(x2, rsv, mrs), g1v[2], be1v[2]));
            float y3 = silu_f(fmaf(fmaf(x3, rsv, mrs), g1v[3], be1v[3]));
            *(uint2*)&XAw[(warp * 8 + it) * 68 + lane * 2] =
                make_uint2(packbf(y0, y1), packbf(y2, y3));
        }
        __syncthreads();   // sync1

        // ---- GEMM1: acc = X1 @ W2 ----
        float acc[2][4][4];
#pragma unroll
        for (int mt = 0; mt < 2; mt++)
#pragma unroll
            for (int nt = 0; nt < 4; nt++)
#pragma unroll
                for (int u = 0; u < 4; u++) acc[mt][nt][u] = 0.f;
#pragma unroll
        for (int kb = 0; kb < 8; kb++) {
            uint32_t a[2][4], b[2][4];
            ldsm4(a[0], aAddr[0] + kb * 32);
            ldsm4(a[1], aAddr[1] + kb * 32);
            ldsm4(b[0], bAddr[0] + kb * 32);
            ldsm4(b[1], bAddr[1] + kb * 32);
#pragma unroll
            for (int mt = 0; mt < 2; mt++)
#pragma unroll
                for (int np = 0; np < 2; np++) {
                    mma16816(acc[mt][2 * np], a[mt], &b[np][0]);
                    mma16816(acc[mt][2 * np + 1], a[mt], &b[np][2]);
                }
        }
        // bias + per-row partial sums (for LN2); params from smem
        float ps[4] = {0.f, 0.f, 0.f, 0.f}, pq[4] = {0.f, 0.f, 0.f, 0.f};
#pragma unroll
        for (int mt = 0; mt < 2; mt++)
#pragma unroll
            for (int nt = 0; nt < 4; nt++) {
                float2 bb = *(const float2*)&sb2[C0 + 8 * nt + 2 * t];
                float v0 = acc[mt][nt][0] + bb.x;
                float v1 = acc[mt][nt][1] + bb.y;
                float v2 = acc[mt][nt][2] + bb.x;
                float v3 = acc[mt][nt][3] + bb.y;
                acc[mt][nt][0] = v0; acc[mt][nt][1] = v1;
                acc[mt][nt][2] = v2; acc[mt][nt][3] = v3;
                ps[2 * mt] += v0 + v1; pq[2 * mt] += v0 * v0 + v1 * v1;
                ps[2 * mt + 1] += v2 + v3; pq[2 * mt + 1] += v2 * v2 + v3 * v3;
            }
#pragma unroll
        for (int rl = 0; rl < 4; rl++) {
            ps[rl] += __shfl_xor_sync(0xffffffffu, ps[rl], 1);
            ps[rl] += __shfl_xor_sync(0xffffffffu, ps[rl], 2);
            pq[rl] += __shfl_xor_sync(0xffffffffu, pq[rl], 1);
            pq[rl] += __shfl_xor_sync(0xffffffffu, pq[rl], 2);
        }
        if (t == 0) {
#pragma unroll
            for (int rl = 0; rl < 4; rl++) {
                int row = R0 + 16 * (rl >> 1) + 8 * (rl & 1) + g;
                *(float2*)&partp[row * 8 + wc * 2] = make_float2(ps[rl], pq[rl]);
            }
        }
        __syncthreads();   // sync2

        // ---- LN2 + SiLU from registers, write X2 (bf16) into XA ----
        float rsl[4], mrl[4];
#pragma unroll
        for (int rl = 0; rl < 4; rl++) {
            int row = R0 + 16 * (rl >> 1) + 8 * (rl & 1) + g;
            float4 pA = *(const float4*)&partp[row * 8];
            float4 pB = *(const float4*)&partp[row * 8 + 4];
            float s = pA.x + pA.z + pB.x + pB.z;
            float q = pA.y + pA.w + pB.y + pB.w;
            float mean = s * (1.f / 128.f);
            float var = q * (1.f / 128.f) - mean * mean;
            rsl[rl] = rsqrtf(var + 1e-5f);
            mrl[rl] = -mean * rsl[rl];
        }
#pragma unroll
        for (int mt = 0; mt < 2; mt++)
#pragma unroll
            for (int nt = 0; nt < 4; nt++) {
                int rl0 = 2 * mt, rl1 = 2 * mt + 1;
                float2 gg = *(const float2*)&sg2[C0 + 8 * nt + 2 * t];
                float2 ee = *(const float2*)&sbe2[C0 + 8 * nt + 2 * t];
                float y0 = silu_f(fmaf(fmaf(acc[mt][nt][0], rsl[rl0], mrl[rl0]), gg.x, ee.x));
                float y1 = silu_f(fmaf(fmaf(acc[mt][nt][1], rsl[rl0], mrl[rl0]), gg.y, ee.y));
                float y2 = silu_f(fmaf(fmaf(acc[mt][nt][2], rsl[rl1], mrl[rl1]), gg.x, ee.x));
                float y3 = silu_f(fmaf(fmaf(acc[mt][nt][3], rsl[rl1], mrl[rl1]), gg.y, ee.y));
                int row = R0 + 16 * mt + g;
                int cw = (C0 + 8 * nt + 2 * t) >> 1;
                XAw[row * 68 + cw] = packbf(y0, y1);
                XAw[(row + 8) * 68 + cw] = packbf(y2, y3);
            }
        __syncthreads();   // sync3

        // ---- GEMM2 (warps 0-3) + coord_diff staging (warps 4-5) ----
        if (warp < 4) {
            float a2[2][4];
#pragma unroll
            for (int nt = 0; nt < 2; nt++)
#pragma unroll
                for (int u = 0; u < 4; u++) a2[nt][u] = 0.f;
#pragma unroll
            for (int kb = 0; kb < 8; kb++) {
                uint32_t aa[4], bb[4];
                ldsm4(aa, aAddr2 + kb * 32);
                ldsm4(bb, bAddr3 + kb * 32);
                mma16816(a2[0], aa, &bb[0]);
                mma16816(a2[1], aa, &bb[2]);
            }
            int row = warp * 16 + g;
#pragma unroll
            for (int nt = 0; nt < 2; nt++) {
                int cc = 8 * nt + 2 * t;
                X3s[row * 17 + cc] = a2[nt][0];
                X3s[row * 17 + cc + 1] = a2[nt][1];
                X3s[(row + 8) * 17 + cc] = a2[nt][2];
                X3s[(row + 8) * 17 + cc + 1] = a2[nt][3];
            }
        } else if (warp < 6) {
            int el2 = tid - 128;
            const float* cdp = coord_diff + (size_t)(ebase + el2) * 9;
#pragma unroll
            for (int c9 = 0; c9 < 9; c9++) cds[el2 * 13 + c9] = __ldg(cdp + c9);
        }
        __syncthreads();   // sync4

        // ---- scatter (warps 4-5) ----
        if (warp >= 4 && warp < 6) {
            int el2 = tid - 128;
            int e2 = ebase + el2;
            int r2 = __ldg(rowI + e2);
            float em = __ldg(edge_mask + e2);
            float ph[9], cd[9];
#pragma unroll
            for (int c9 = 0; c9 < 9; c9++) ph[c9] = X3s[el2 * 17 + c9];
#pragma unroll
            for (int c9 = 0; c9 < 9; c9++) cd[c9] = cds[el2 * 13 + c9];
            float* aggp = g_agg + (size_t)r2 * 9;
#pragma unroll
            for (int l = 0; l < 3; l++)
#pragma unroll
                for (int k = 0; k < 3; k++) {
                    float tr = cd[k] * ph[l] + cd[3 + k] * ph[3 + l] + cd[6 + k] * ph[6 + l];
                    atomicAdd(aggp + l * 3 + k, tr * em);
                }
        }
        // no extra barrier needed (see round-2 analysis)
    }
}

__global__ void finalize_kernel(const float* __restrict__ coord,
                                const float* __restrict__ node_mask,
                                float* __restrict__ out) {
    int i = blockIdx.x * 256 + threadIdx.x;
    if (i < NNODES * 9) {
        out[i] = (coord[i] + g_agg[i] * 0.01f) * node_mask[i / 9];
    }
}

extern "C" void kernel_launch(void* const* d_in, const int* in_sizes, int n_in,
                              void* d_out, int out_size) {
    const float* h          = (const float*)d_in[0];
    const float* coord      = (const float*)d_in[1];
    const float* coord_diff = (const float*)d_in[2];
    const float* edge_attr  = (const float*)d_in[3];
    const float* edge_mask  = (const float*)d_in[4];
    const float* node_mask  = (const float*)d_in[5];
    const int*   rowI       = (const int*)d_in[6];
    const int*   colI       = (const int*)d_in[7];
    const float* W1  = (const float*)d_in[8];
    const float* b1  = (const float*)d_in[9];
    const float* g1  = (const float*)d_in[10];
    const float* be1 = (const float*)d_in[11];
    const float* W2  = (const float*)d_in[12];
    const float* b2  = (const float*)d_in[13];
    const float* g2  = (const float*)d_in[14];
    const float* be2 = (const float*)d_in[15];
    const float* W3  = (const float*)d_in[16];
    float* out = (float*)d_out;

    cudaFuncSetAttribute(hab_kernel, cudaFuncAttributeMaxDynamicSharedMemorySize, HAB_SMEM);
    cudaFuncSetAttribute(edge_kernel, cudaFuncAttributeMaxDynamicSharedMemorySize, EDGE_SMEM);

    prep_kernel<<<(NNODES * 9 + 255) / 256, 256>>>(W1);
    hab_kernel<<<dim3((NNODES + 63) / 64, 2), 256, HAB_SMEM>>>(h, b1);
    edge_kernel<<<444, 256, EDGE_SMEM>>>(W1, g1, be1, W2, b2, g2, be2, W3,
                                         rowI, colI, edge_attr, edge_mask, coord_diff);
    finalize_kernel<<<(NNODES * 9 + 255) / 256, 256>>>(coord, node_mask, out);
}